// round 7
// baseline (speedup 1.0000x reference)
#include <cuda_runtime.h>
#include <cuda_fp16.h>
#include <cstdint>

// NearestEmbed: x (64,64,32,32) f32, emb (64,512) f32
// out f32 = [ quantized 4194304 | argmin 65536 (as float) ]
//
// R7: HMMA coarse + exact-rescue (as R6), occupancy-doubled:
//   - __launch_bounds__(512,2) -> <=64 regs/thread -> 2 CTAs/SM (32 warps)
//   - fp32 codebook no longer cached in smem (global/L2 instead): smem ~72KB
//   - grid 256 CTAs x 1 tile of 256 rows

#define THREADS 512            // 16 warps, warp handles 16 rows
#define TILE_M 256
#define GRID 256               // 256 tiles total, 1 per CTA
#define EMB_D 64
#define EMB_K 512
#define HW 1024
#define MARGIN 0.04f

// smem layout (bytes)
#define SM_FRAGS 0                       // u32 frags[64 nt][4 ks][32 lane][2] = 64KB
#define SM_NORMS 65536                   // f32 [512] = 2KB
#define SM_WIN   (SM_NORMS + 2048)       // i32 [256]
#define SM_QUEUE (SM_WIN + 1024)         // i32 [256]
#define SM_QCNT  (SM_QUEUE + 1024)       // i32
#define SM_XS    (SM_QCNT + 16)          // f32 [16 warps][64] = 4KB
#define SM_TOTAL (SM_XS + 4096)

__device__ __forceinline__ uint32_t packh2(float a, float b) {
    __half2 h = __floats2half2_rn(a, b);
    return *reinterpret_cast<uint32_t*>(&h);
}

__device__ __forceinline__ void hmma16816(float& c0, float& c1, float& c2, float& c3,
                                          uint32_t a0, uint32_t a1, uint32_t a2, uint32_t a3,
                                          uint32_t b0, uint32_t b1) {
    asm volatile("mma.sync.aligned.m16n8k16.row.col.f32.f16.f16.f32 "
                 "{%0,%1,%2,%3}, {%4,%5,%6,%7}, {%8,%9}, {%0,%1,%2,%3};"
                 : "+f"(c0), "+f"(c1), "+f"(c2), "+f"(c3)
                 : "r"(a0), "r"(a1), "r"(a2), "r"(a3), "r"(b0), "r"(b1));
}

__global__ __launch_bounds__(THREADS, 2)
void vq_hmma_kernel(const float* __restrict__ x,
                    const float* __restrict__ emb,
                    float* __restrict__ out_q,
                    float* __restrict__ out_idx)
{
    extern __shared__ char smem[];
    uint32_t* frags   = reinterpret_cast<uint32_t*>(smem + SM_FRAGS);
    float*    norms   = reinterpret_cast<float*>(smem + SM_NORMS);
    int*      winners = reinterpret_cast<int*>(smem + SM_WIN);
    int*      queue   = reinterpret_cast<int*>(smem + SM_QUEUE);
    int*      qcnt    = reinterpret_cast<int*>(smem + SM_QCNT);
    float*    xscr    = reinterpret_cast<float*>(smem + SM_XS);

    const int tid  = threadIdx.x;
    const int warp = tid >> 5;
    const int lane = tid & 31;
    const int gidq = lane & 3;
    const int grp  = lane >> 2;

    // ---- Prologue ----
    if (tid == 0) *qcnt = 0;
    for (int k = tid; k < EMB_K; k += THREADS) {
        float s = 0.f;
        #pragma unroll
        for (int d = 0; d < EMB_D; d++) {
            float v = __ldg(emb + d * EMB_K + k);
            s = fmaf(v, v, s);
        }
        norms[k] = s;
    }
    // B fragments: frags[((nt*4+ks)*32 + lane)*2 + j]
    //   n = nt*8 + lane/4 ; d0 = ks*16 + 2*(lane%4) + 8*j
    for (int f = tid; f < 64 * 4 * 32 * 2; f += THREADS) {
        int j  = f & 1;
        int ln = (f >> 1) & 31;
        int ks = (f >> 6) & 3;
        int nt = f >> 8;
        int n  = nt * 8 + (ln >> 2);
        int d0 = ks * 16 + 2 * (ln & 3) + 8 * j;
        frags[f] = packh2(__ldg(emb + d0 * EMB_K + n), __ldg(emb + (d0 + 1) * EMB_K + n));
    }
    __syncthreads();

    const int row_base = blockIdx.x * TILE_M;
    const int b = row_base >> 10;
    const int hw_base = row_base & (HW - 1);
    const float* xb = x + (size_t)b * (EMB_D * HW) + hw_base;   // x(row,d)=xb[d*HW+row]

    // ---- A fragments: this warp's 16 rows ----
    const float* xw = xb + warp * 16;
    uint32_t A[4][4];
    {
        const int q2 = gidq * 2;
        #pragma unroll
        for (int ks = 0; ks < 4; ks++) {
            int d = ks * 16 + q2;
            A[ks][0] = packh2(xw[d * HW + grp],           xw[(d + 1) * HW + grp]);
            A[ks][1] = packh2(xw[d * HW + grp + 8],       xw[(d + 1) * HW + grp + 8]);
            A[ks][2] = packh2(xw[(d + 8) * HW + grp],     xw[(d + 9) * HW + grp]);
            A[ks][3] = packh2(xw[(d + 8) * HW + grp + 8], xw[(d + 9) * HW + grp + 8]);
        }
    }

    // ---- coarse scan over 64 n-tiles ----
    float b1a = __int_as_float(0x7f800000), b2a = b1a; int k1a = 0;
    float b1b = b1a, b2b = b1a; int k1b = 0;

    const uint2* fr2 = reinterpret_cast<const uint2*>(frags);
    #pragma unroll 2
    for (int nt = 0; nt < 64; nt++) {
        float c0 = 0.f, c1 = 0.f, c2 = 0.f, c3 = 0.f;
        #pragma unroll
        for (int ks = 0; ks < 4; ks++) {
            uint2 bb = fr2[(nt * 4 + ks) * 32 + lane];
            hmma16816(c0, c1, c2, c3, A[ks][0], A[ks][1], A[ks][2], A[ks][3], bb.x, bb.y);
        }
        const int n0 = nt * 8 + gidq * 2;
        float2 nr = *reinterpret_cast<const float2*>(norms + n0);
        float s0 = fmaf(-2.f, c0, nr.x);
        float s1 = fmaf(-2.f, c1, nr.y);
        float s2 = fmaf(-2.f, c2, nr.x);
        float s3 = fmaf(-2.f, c3, nr.y);
        if (s0 < b1a) { b2a = b1a; b1a = s0; k1a = n0; } else b2a = fminf(b2a, s0);
        if (s1 < b1a) { b2a = b1a; b1a = s1; k1a = n0 + 1; } else b2a = fminf(b2a, s1);
        if (s2 < b1b) { b2b = b1b; b1b = s2; k1b = n0; } else b2b = fminf(b2b, s2);
        if (s3 < b1b) { b2b = b1b; b1b = s3; k1b = n0 + 1; } else b2b = fminf(b2b, s3);
    }

    // ---- merge across the 4 lanes of each row-group ----
    #pragma unroll
    for (int off = 1; off <= 2; off <<= 1) {
        float ob1 = __shfl_xor_sync(0xffffffffu, b1a, off);
        int   ok1 = __shfl_xor_sync(0xffffffffu, k1a, off);
        float ob2 = __shfl_xor_sync(0xffffffffu, b2a, off);
        float nb2 = fminf(fmaxf(b1a, ob1), fminf(b2a, ob2));
        bool take = (ob1 < b1a) || (ob1 == b1a && ok1 < k1a);
        b1a = take ? ob1 : b1a; k1a = take ? ok1 : k1a; b2a = nb2;

        float pb1 = __shfl_xor_sync(0xffffffffu, b1b, off);
        int   pk1 = __shfl_xor_sync(0xffffffffu, k1b, off);
        float pb2 = __shfl_xor_sync(0xffffffffu, b2b, off);
        float qb2 = fminf(fmaxf(b1b, pb1), fminf(b2b, pb2));
        bool tk2 = (pb1 < b1b) || (pb1 == b1b && pk1 < k1b);
        b1b = tk2 ? pb1 : b1b; k1b = tk2 ? pk1 : k1b; b2b = qb2;
    }

    if (gidq == 0) {
        int lr = warp * 16 + grp;
        if (b2a - b1a <= MARGIN) { int qi = atomicAdd(qcnt, 1); queue[qi] = lr; }
        else winners[lr] = k1a;
        int lr2 = lr + 8;
        if (b2b - b1b <= MARGIN) { int qi = atomicAdd(qcnt, 1); queue[qi] = lr2; }
        else winners[lr2] = k1b;
    }
    __syncthreads();

    // ---- exact fp32 rescan for ambiguous rows (rare; emb from global, coalesced) ----
    const int nq = *qcnt;
    for (int i = warp; i < nq; i += 16) {
        int lr = queue[i];
        const float* xg = xb + lr;
        float* xs = xscr + warp * 64;
        xs[lane] = xg[(size_t)lane * HW];
        xs[lane + 32] = xg[(size_t)(lane + 32) * HW];
        __syncwarp();
        float best = __int_as_float(0x7f800000);
        int bk = 0;
        #pragma unroll
        for (int j = 0; j < 16; j++) {
            int k = lane + 32 * j;
            float acc = 0.f;
            #pragma unroll
            for (int d = 0; d < EMB_D; d++)
                acc = fmaf(xs[d], __ldg(emb + d * EMB_K + k), acc);
            float sc = fmaf(-2.f, acc, norms[k]);
            if (sc < best) { best = sc; bk = k; }
        }
        #pragma unroll
        for (int off = 16; off >= 1; off >>= 1) {
            float os = __shfl_xor_sync(0xffffffffu, best, off);
            int   ok = __shfl_xor_sync(0xffffffffu, bk, off);
            bool take = (os < best) || (os == best && ok < bk);
            best = take ? os : best;
            bk = take ? ok : bk;
        }
        if (lane == 0) winners[lr] = bk;
        __syncwarp();
    }
    __syncthreads();

    // ---- outputs (gather from global emb; scattered but L2-resident, high MLP) ----
    float* oq = out_q + (size_t)b * (EMB_D * HW) + hw_base;
    for (int i = tid; i < TILE_M * EMB_D; i += THREADS) {
        int r = i & (TILE_M - 1);
        int d = i >> 8;
        oq[(size_t)d * HW + r] = __ldg(emb + d * EMB_K + winners[r]);
    }
    if (tid < TILE_M) out_idx[row_base + tid] = (float)winners[tid];
}

extern "C" void kernel_launch(void* const* d_in, const int* in_sizes, int n_in,
                              void* d_out, int out_size)
{
    const float* x   = (const float*)d_in[0];   // 4194304 f32
    const float* emb = (const float*)d_in[1];   // 32768 f32
    float* out_q = (float*)d_out;
    float* out_i = (float*)d_out + (size_t)4194304;

    cudaFuncSetAttribute(vq_hmma_kernel,
                         cudaFuncAttributeMaxDynamicSharedMemorySize, SM_TOTAL);
    vq_hmma_kernel<<<GRID, THREADS, SM_TOTAL>>>(x, emb, out_q, out_i);
}

// round 8
// speedup vs baseline: 1.6845x; 1.6845x over previous
#include <cuda_runtime.h>
#include <cuda_fp16.h>
#include <cstdint>

// NearestEmbed: x (64,64,32,32) f32, emb (64,512) f32
// out f32 = [ quantized 4194304 | argmin 65536 (as float) ]
//
// R8: R6 (HMMA coarse + exact fp32 rescue, 1 CTA/SM, 128 regs) with the
// loop-carried top-2 chain split into two independent states (even/odd nt),
// merged after the loop. Doubles critical-path ILP at +6 regs.

#define THREADS 512            // 16 warps, warp handles 16 rows
#define TILE_M 256             // rows per CTA tile
#define GRID 128
#define TILES_PER_CTA 2        // 256 tiles total / 128 CTAs
#define EMB_D 64
#define EMB_K 512
#define HW 1024
#define MARGIN 0.04f

// smem layout (bytes)
#define SM_FRAGS 0                       // u32 frags[64 nt][4 ks][32 lane][2] = 64KB
#define SM_EMB   65536                   // f32 emb_s[64][512] = 128KB
#define SM_NORMS (SM_EMB + 131072)       // f32 [512] = 2KB
#define SM_WIN   (SM_NORMS + 2048)       // i32 [256]
#define SM_QUEUE (SM_WIN + 1024)         // i32 [256]
#define SM_QCNT  (SM_QUEUE + 1024)       // i32
#define SM_XS    (SM_QCNT + 16)          // f32 [16 warps][64] = 4KB
#define SM_TOTAL (SM_XS + 4096)

__device__ __forceinline__ uint32_t packh2(float a, float b) {
    __half2 h = __floats2half2_rn(a, b);
    return *reinterpret_cast<uint32_t*>(&h);
}

__device__ __forceinline__ void hmma16816(float& c0, float& c1, float& c2, float& c3,
                                          uint32_t a0, uint32_t a1, uint32_t a2, uint32_t a3,
                                          uint32_t b0, uint32_t b1) {
    asm volatile("mma.sync.aligned.m16n8k16.row.col.f32.f16.f16.f32 "
                 "{%0,%1,%2,%3}, {%4,%5,%6,%7}, {%8,%9}, {%0,%1,%2,%3};"
                 : "+f"(c0), "+f"(c1), "+f"(c2), "+f"(c3)
                 : "r"(a0), "r"(a1), "r"(a2), "r"(a3), "r"(b0), "r"(b1));
}

__global__ __launch_bounds__(THREADS, 1)
void vq_hmma_kernel(const float* __restrict__ x,
                    const float* __restrict__ emb,
                    float* __restrict__ out_q,
                    float* __restrict__ out_idx)
{
    extern __shared__ char smem[];
    uint32_t* frags   = reinterpret_cast<uint32_t*>(smem + SM_FRAGS);
    float*    emb_s   = reinterpret_cast<float*>(smem + SM_EMB);
    float*    norms   = reinterpret_cast<float*>(smem + SM_NORMS);
    int*      winners = reinterpret_cast<int*>(smem + SM_WIN);
    int*      queue   = reinterpret_cast<int*>(smem + SM_QUEUE);
    int*      qcnt    = reinterpret_cast<int*>(smem + SM_QCNT);
    float*    xscr    = reinterpret_cast<float*>(smem + SM_XS);

    const int tid  = threadIdx.x;
    const int warp = tid >> 5;
    const int lane = tid & 31;
    const int gidq = lane & 3;
    const int grp  = lane >> 2;

    // ---- Prologue (once per CTA) ----
    for (int i = tid; i < EMB_D * EMB_K; i += THREADS) emb_s[i] = emb[i];
    if (tid == 0) *qcnt = 0;
    __syncthreads();

    for (int k = tid; k < EMB_K; k += THREADS) {
        float s = 0.f;
        #pragma unroll
        for (int d = 0; d < EMB_D; d++) {
            float v = emb_s[d * EMB_K + k];
            s = fmaf(v, v, s);
        }
        norms[k] = s;
    }
    // B fragments: frags[((nt*4+ks)*32 + lane)*2 + j]
    for (int f = tid; f < 64 * 4 * 32 * 2; f += THREADS) {
        int j  = f & 1;
        int ln = (f >> 1) & 31;
        int ks = (f >> 6) & 3;
        int nt = f >> 8;
        int n  = nt * 8 + (ln >> 2);
        int d0 = ks * 16 + 2 * (ln & 3) + 8 * j;
        frags[f] = packh2(emb_s[d0 * EMB_K + n], emb_s[(d0 + 1) * EMB_K + n]);
    }
    __syncthreads();

    for (int it = 0; it < TILES_PER_CTA; it++) {
        const int tile = blockIdx.x * TILES_PER_CTA + it;
        const int row_base = tile * TILE_M;
        const int b = row_base >> 10;
        const int hw_base = row_base & (HW - 1);
        const float* xb = x + (size_t)b * (EMB_D * HW) + hw_base;   // x(row,d)=xb[d*HW+row]

        // ---- A fragments: this warp's 16 rows ----
        const float* xw = xb + warp * 16;
        uint32_t A[4][4];
        {
            const int q2 = gidq * 2;
            #pragma unroll
            for (int ks = 0; ks < 4; ks++) {
                int d = ks * 16 + q2;
                A[ks][0] = packh2(xw[d * HW + grp],           xw[(d + 1) * HW + grp]);
                A[ks][1] = packh2(xw[d * HW + grp + 8],       xw[(d + 1) * HW + grp + 8]);
                A[ks][2] = packh2(xw[(d + 8) * HW + grp],     xw[(d + 9) * HW + grp]);
                A[ks][3] = packh2(xw[(d + 8) * HW + grp + 8], xw[(d + 9) * HW + grp + 8]);
            }
        }

        // ---- coarse scan: two independent top-2 states per row (even/odd nt) ----
        float b1a[2], b2a[2], b1b[2], b2b[2];
        int   k1a[2], k1b[2];
        #pragma unroll
        for (int p = 0; p < 2; p++) {
            b1a[p] = b2a[p] = b1b[p] = b2b[p] = __int_as_float(0x7f800000);
            k1a[p] = k1b[p] = 0;
        }

        const uint2* fr2 = reinterpret_cast<const uint2*>(frags);
        #pragma unroll 4
        for (int nt = 0; nt < 64; nt++) {
            const int p = nt & 1;
            float c0 = 0.f, c1 = 0.f, c2 = 0.f, c3 = 0.f;
            #pragma unroll
            for (int ks = 0; ks < 4; ks++) {
                uint2 bb = fr2[(nt * 4 + ks) * 32 + lane];
                hmma16816(c0, c1, c2, c3, A[ks][0], A[ks][1], A[ks][2], A[ks][3], bb.x, bb.y);
            }
            const int n0 = nt * 8 + gidq * 2;
            float2 nr = *reinterpret_cast<const float2*>(norms + n0);
            float s0 = fmaf(-2.f, c0, nr.x);
            float s1 = fmaf(-2.f, c1, nr.y);
            float s2 = fmaf(-2.f, c2, nr.x);
            float s3 = fmaf(-2.f, c3, nr.y);
            if (s0 < b1a[p]) { b2a[p] = b1a[p]; b1a[p] = s0; k1a[p] = n0; } else b2a[p] = fminf(b2a[p], s0);
            if (s1 < b1a[p]) { b2a[p] = b1a[p]; b1a[p] = s1; k1a[p] = n0 + 1; } else b2a[p] = fminf(b2a[p], s1);
            if (s2 < b1b[p]) { b2b[p] = b1b[p]; b1b[p] = s2; k1b[p] = n0; } else b2b[p] = fminf(b2b[p], s2);
            if (s3 < b1b[p]) { b2b[p] = b1b[p]; b1b[p] = s3; k1b[p] = n0 + 1; } else b2b[p] = fminf(b2b[p], s3);
        }

        // merge odd state into even (lowest-index wins ties)
        float b1A, b2A, b1B, b2B; int k1A, k1B;
        {
            bool ta = (b1a[1] < b1a[0]) || (b1a[1] == b1a[0] && k1a[1] < k1a[0]);
            b1A = ta ? b1a[1] : b1a[0];
            k1A = ta ? k1a[1] : k1a[0];
            b2A = fminf(fmaxf(b1a[0], b1a[1]), fminf(b2a[0], b2a[1]));
            bool tb = (b1b[1] < b1b[0]) || (b1b[1] == b1b[0] && k1b[1] < k1b[0]);
            b1B = tb ? b1b[1] : b1b[0];
            k1B = tb ? k1b[1] : k1b[0];
            b2B = fminf(fmaxf(b1b[0], b1b[1]), fminf(b2b[0], b2b[1]));
        }

        // ---- merge across the 4 lanes of each row-group ----
        #pragma unroll
        for (int off = 1; off <= 2; off <<= 1) {
            float ob1 = __shfl_xor_sync(0xffffffffu, b1A, off);
            int   ok1 = __shfl_xor_sync(0xffffffffu, k1A, off);
            float ob2 = __shfl_xor_sync(0xffffffffu, b2A, off);
            float nb2 = fminf(fmaxf(b1A, ob1), fminf(b2A, ob2));
            bool take = (ob1 < b1A) || (ob1 == b1A && ok1 < k1A);
            b1A = take ? ob1 : b1A; k1A = take ? ok1 : k1A; b2A = nb2;

            float pb1 = __shfl_xor_sync(0xffffffffu, b1B, off);
            int   pk1 = __shfl_xor_sync(0xffffffffu, k1B, off);
            float pb2 = __shfl_xor_sync(0xffffffffu, b2B, off);
            float qb2 = fminf(fmaxf(b1B, pb1), fminf(b2B, pb2));
            bool tk2 = (pb1 < b1B) || (pb1 == b1B && pk1 < k1B);
            b1B = tk2 ? pb1 : b1B; k1B = tk2 ? pk1 : k1B; b2B = qb2;
        }

        if (gidq == 0) {
            int lr = warp * 16 + grp;
            if (b2A - b1A <= MARGIN) { int qi = atomicAdd(qcnt, 1); queue[qi] = lr; }
            else winners[lr] = k1A;
            int lr2 = lr + 8;
            if (b2B - b1B <= MARGIN) { int qi = atomicAdd(qcnt, 1); queue[qi] = lr2; }
            else winners[lr2] = k1B;
        }
        __syncthreads();

        // ---- exact fp32 rescan for ambiguous rows (rare) ----
        const int nq = *qcnt;
        for (int i = warp; i < nq; i += 16) {
            int lr = queue[i];
            const float* xg = xb + lr;
            float* xs = xscr + warp * 64;
            xs[lane] = xg[(size_t)lane * HW];
            xs[lane + 32] = xg[(size_t)(lane + 32) * HW];
            __syncwarp();
            float best = __int_as_float(0x7f800000);
            int bk = 0;
            #pragma unroll
            for (int j = 0; j < 16; j++) {
                int k = lane + 32 * j;
                float acc = 0.f;
                #pragma unroll
                for (int d = 0; d < EMB_D; d++)
                    acc = fmaf(xs[d], emb_s[d * EMB_K + k], acc);
                float sc = fmaf(-2.f, acc, norms[k]);
                if (sc < best) { best = sc; bk = k; }
            }
            #pragma unroll
            for (int off = 16; off >= 1; off >>= 1) {
                float os = __shfl_xor_sync(0xffffffffu, best, off);
                int   ok = __shfl_xor_sync(0xffffffffu, bk, off);
                bool take = (os < best) || (os == best && ok < bk);
                best = take ? os : best;
                bk = take ? ok : bk;
            }
            if (lane == 0) winners[lr] = bk;
            __syncwarp();
        }
        __syncthreads();

        // ---- outputs ----
        float* oq = out_q + (size_t)b * (EMB_D * HW) + hw_base;
        for (int i = tid; i < TILE_M * EMB_D; i += THREADS) {
            int r = i & (TILE_M - 1);
            int d = i >> 8;
            oq[(size_t)d * HW + r] = emb_s[d * EMB_K + winners[r]];
        }
        if (tid < TILE_M) out_idx[row_base + tid] = (float)winners[tid];
        if (tid == 0) *qcnt = 0;
        __syncthreads();
    }
}

extern "C" void kernel_launch(void* const* d_in, const int* in_sizes, int n_in,
                              void* d_out, int out_size)
{
    const float* x   = (const float*)d_in[0];   // 4194304 f32
    const float* emb = (const float*)d_in[1];   // 32768 f32
    float* out_q = (float*)d_out;
    float* out_i = (float*)d_out + (size_t)4194304;

    cudaFuncSetAttribute(vq_hmma_kernel,
                         cudaFuncAttributeMaxDynamicSharedMemorySize, SM_TOTAL);
    vq_hmma_kernel<<<GRID, THREADS, SM_TOTAL>>>(x, emb, out_q, out_i);
}